// round 10
// baseline (speedup 1.0000x reference)
#include <cuda_runtime.h>
#include <cstdint>

// Problem shape (fixed): x[B=64, C=256, H=56, W=56] fp32
#define C_    256
#define B_    64
#define HW4_  784        // float4 per plane
#define HW8_  392        // float8 per plane
#define NPC_  200704     // B*HW per channel
#define EPS_  1e-5f
#define N4_   12845056   // total float4
#define NBLK_ 6272       // norm blocks (2048 float4 each)
// float4 index where the L2-pinned tail begins (~104 MB kept resident).
// Multiple of 1568 (2-plane block size) so reduce blocks don't straddle it.
#define RESIDENT_START_ 6345248

__device__ float g_psum[C_ * B_];
__device__ float g_psq [C_ * B_];
__device__ float g_scale[C_];
__device__ float g_bias [C_];

__device__ __forceinline__ float fsum4(const float4 v) { return (v.x + v.y) + (v.z + v.w); }
__device__ __forceinline__ float fsq4 (const float4 v) { return v.x*v.x + v.y*v.y + v.z*v.z + v.w*v.w; }

// 256-bit L2-hinted loads (sm_103a requires v8.b32 with L2::evict_* hints).
// p must be 32B-aligned. Returns 2 float4s.
__device__ __forceinline__ void ld_keep8(const float4* p, float4& a, float4& b) {
    uint32_t r0,r1,r2,r3,r4,r5,r6,r7;
    asm volatile("ld.global.nc.L2::evict_last.v8.b32 {%0,%1,%2,%3,%4,%5,%6,%7}, [%8];"
                 : "=r"(r0),"=r"(r1),"=r"(r2),"=r"(r3),
                   "=r"(r4),"=r"(r5),"=r"(r6),"=r"(r7) : "l"(p));
    a.x=__uint_as_float(r0); a.y=__uint_as_float(r1);
    a.z=__uint_as_float(r2); a.w=__uint_as_float(r3);
    b.x=__uint_as_float(r4); b.y=__uint_as_float(r5);
    b.z=__uint_as_float(r6); b.w=__uint_as_float(r7);
}
__device__ __forceinline__ void ld_first8(const float4* p, float4& a, float4& b) {
    uint32_t r0,r1,r2,r3,r4,r5,r6,r7;
    asm volatile("ld.global.nc.L2::evict_first.v8.b32 {%0,%1,%2,%3,%4,%5,%6,%7}, [%8];"
                 : "=r"(r0),"=r"(r1),"=r"(r2),"=r"(r3),
                   "=r"(r4),"=r"(r5),"=r"(r6),"=r"(r7) : "l"(p));
    a.x=__uint_as_float(r0); a.y=__uint_as_float(r1);
    a.z=__uint_as_float(r2); a.w=__uint_as_float(r3);
    b.x=__uint_as_float(r4); b.y=__uint_as_float(r5);
    b.z=__uint_as_float(r6); b.w=__uint_as_float(r7);
}

// ---------------------------------------------------------------------------
// Pass 1: two planes per block (b, 2c), (b, 2c+1) = 784 float8, 256 threads.
// Grid (c2 fast, b slow) ~ linear address order. Front: __ldcs streaming.
// Tail (~104 MB): evict_last (pinned in L2 for the reversed norm pass).
// float8 u = t + 256j; plane0 iff u < 392: j=0 all, j=1 iff t<136, j>=2 none.
// ---------------------------------------------------------------------------
__global__ __launch_bounds__(256) void reduce_k(const float4* __restrict__ x) {
    const int c2 = blockIdx.x;
    const int b  = blockIdx.y;
    const size_t start4 = ((size_t)b * C_ + 2 * c2) * HW4_;
    const float4* p = x + start4;
    const int t = threadIdx.x;

    float4 a0,b0, a1,b1, a2,b2, a3,b3;
    a3 = b3 = make_float4(0.f,0.f,0.f,0.f);
    if (start4 >= (size_t)RESIDENT_START_) {
        ld_keep8(p + 2*t,          a0, b0);
        ld_keep8(p + 2*(t + 256),  a1, b1);
        ld_keep8(p + 2*(t + 512),  a2, b2);
        if (t < 16) ld_keep8(p + 2*(t + 768), a3, b3);
    } else {
        a0 = __ldcs(p + 2*t);           b0 = __ldcs(p + 2*t + 1);
        a1 = __ldcs(p + 2*(t+256));     b1 = __ldcs(p + 2*(t+256) + 1);
        a2 = __ldcs(p + 2*(t+512));     b2 = __ldcs(p + 2*(t+512) + 1);
        if (t < 16) { a3 = __ldcs(p + 2*(t+768)); b3 = __ldcs(p + 2*(t+768) + 1); }
    }

    // plane assignment: j=0 -> plane0; j=2,3 -> plane1; j=1 -> t<136 ? p0 : p1
    float s0 = fsum4(a0) + fsum4(b0);
    float q0 = fsq4 (a0) + fsq4 (b0);
    float s1 = fsum4(a2) + fsum4(b2) + fsum4(a3) + fsum4(b3);
    float q1 = fsq4 (a2) + fsq4 (b2) + fsq4 (a3) + fsq4 (b3);
    const float sj1 = fsum4(a1) + fsum4(b1);
    const float qj1 = fsq4 (a1) + fsq4 (b1);
    if (t < 136) { s0 += sj1; q0 += qj1; } else { s1 += sj1; q1 += qj1; }

    #pragma unroll
    for (int o = 16; o > 0; o >>= 1) {
        s0 += __shfl_xor_sync(0xffffffffu, s0, o);
        q0 += __shfl_xor_sync(0xffffffffu, q0, o);
        s1 += __shfl_xor_sync(0xffffffffu, s1, o);
        q1 += __shfl_xor_sync(0xffffffffu, q1, o);
    }

    __shared__ float sh[4][8];
    const int w = t >> 5, l = t & 31;
    if (l == 0) { sh[0][w] = s0; sh[1][w] = q0; sh[2][w] = s1; sh[3][w] = q1; }
    __syncthreads();

    if (t < 2) {
        float ts = 0.f, tq = 0.f;
        #pragma unroll
        for (int i = 0; i < 8; i++) { ts += sh[2*t][i]; tq += sh[2*t+1][i]; }
        const int c = 2 * c2 + t;
        g_psum[c * B_ + b] = ts;
        g_psq [c * B_ + b] = tq;
    }
}

// ---------------------------------------------------------------------------
__global__ __launch_bounds__(256) void finalize_k(const float* __restrict__ gamma,
                                                  const float* __restrict__ beta) {
    const int c = threadIdx.x;
    float s = 0.f, sq = 0.f;
    #pragma unroll
    for (int b = 0; b < B_; b++) {
        s  += g_psum[c * B_ + b];
        sq += g_psq [c * B_ + b];
    }
    const float inv_n = 1.f / (float)NPC_;
    const float mean  = s * inv_n;
    const float var   = sq * inv_n - mean * mean;
    const float sc    = gamma[c] * rsqrtf(var + EPS_);
    g_scale[c] = sc;
    g_bias[c]  = beta[c] - mean * sc;
}

// ---------------------------------------------------------------------------
// Pass 2: flat, REVERSED block order (consume pinned tail first).
// 4 x 256-bit evict_first loads per thread (pollution-free everywhere,
// hit+release in the pinned region). Block = 1024 float8 = 2048 float4.
// A float8 never straddles a plane boundary (784 even), so one channel per
// float8: c = (u8/392) & 255.
// ---------------------------------------------------------------------------
__global__ __launch_bounds__(256) void norm_k(const float4* __restrict__ x,
                                              float4* __restrict__ out) {
    const int base8 = (NBLK_ - 1 - (int)blockIdx.x) * 1024 + (int)threadIdx.x;

    float4 a[4], b[4];
    #pragma unroll
    for (int j = 0; j < 4; j++)
        ld_first8(x + 2*(base8 + 256*j), a[j], b[j]);

    #pragma unroll
    for (int j = 0; j < 4; j++) {
        const int u8 = base8 + 256*j;
        const int c  = (u8 / HW8_) & (C_ - 1);
        const float sc = g_scale[c];
        const float bi = g_bias[c];
        a[j].x = fmaf(a[j].x, sc, bi); a[j].y = fmaf(a[j].y, sc, bi);
        a[j].z = fmaf(a[j].z, sc, bi); a[j].w = fmaf(a[j].w, sc, bi);
        b[j].x = fmaf(b[j].x, sc, bi); b[j].y = fmaf(b[j].y, sc, bi);
        b[j].z = fmaf(b[j].z, sc, bi); b[j].w = fmaf(b[j].w, sc, bi);
        __stcs(out + 2*u8,     a[j]);
        __stcs(out + 2*u8 + 1, b[j]);
    }
}

// ---------------------------------------------------------------------------
extern "C" void kernel_launch(void* const* d_in, const int* in_sizes, int n_in,
                              void* d_out, int out_size) {
    const float* x     = (const float*)d_in[0];
    const float* gamma = (const float*)d_in[1];
    const float* beta  = (const float*)d_in[2];
    float* out = (float*)d_out;

    dim3 rgrid(C_ / 2, B_);     // c2 fast, b slow -> execution ~ address order
    reduce_k<<<rgrid, 256>>>((const float4*)x);
    finalize_k<<<1, C_>>>(gamma, beta);
    norm_k<<<NBLK_, 256>>>((const float4*)x, (float4*)out);
}